// round 3
// baseline (speedup 1.0000x reference)
#include <cuda_runtime.h>
#include <stdint.h>

#define N_NODES 50000
#define N_EDGES 400000
#define IN_FEAT 64
#define H_DIM 32

// ---- device scratch (no runtime allocation allowed) ----
__device__ float g_h[N_NODES * H_DIM];     // relu(x@lin0_w + lin0_b)
__device__ float g_S[N_NODES * H_DIM];     // scatter-sum of h[src] at dst
__device__ float g_out[N_NODES * H_DIM];   // node embeddings after NNConv
__device__ float g_We[H_DIM * H_DIM];      // shared per-edge weight matrix

// ============================================================
// K0: W_edge = relu(nn_w1 + nn_b1) @ nn_w2 + nn_b2  (all edges share it,
// since edge_attr == ones((E,1)))
// ============================================================
__global__ void k0_edge_weight(const float* __restrict__ nn_w1,
                               const float* __restrict__ nn_b1,
                               const float* __restrict__ nn_w2,
                               const float* __restrict__ nn_b2) {
    __shared__ float w1[H_DIM];
    int t = threadIdx.x;
    if (t < H_DIM) {
        float v = nn_w1[t] + nn_b1[t];
        w1[t] = v > 0.f ? v : 0.f;
    }
    __syncthreads();
    for (int i = t; i < H_DIM * H_DIM; i += blockDim.x) {
        float acc = nn_b2[i];
        #pragma unroll
        for (int k = 0; k < H_DIM; k++)
            acc += w1[k] * nn_w2[k * (H_DIM * H_DIM) + i];
        g_We[i] = acc;
    }
}

// ============================================================
// K1: h = relu(x @ lin0_w + lin0_b), and zero S.
// One warp per node row; lane = output feature.
// ============================================================
__global__ void k1_lin0(const float* __restrict__ x,
                        const float* __restrict__ lin0_w,
                        const float* __restrict__ lin0_b,
                        int n_nodes) {
    __shared__ float sw[IN_FEAT * H_DIM];  // 8 KB
    for (int i = threadIdx.x; i < IN_FEAT * H_DIM; i += blockDim.x)
        sw[i] = lin0_w[i];
    __syncthreads();

    int warp = threadIdx.x >> 5;
    int lane = threadIdx.x & 31;
    int row = blockIdx.x * (blockDim.x >> 5) + warp;
    if (row >= n_nodes) return;

    const float* xr = x + (size_t)row * IN_FEAT;
    float acc = lin0_b[lane];
    #pragma unroll 8
    for (int k = 0; k < IN_FEAT; k++)
        acc = fmaf(xr[k], sw[k * H_DIM + lane], acc);  // xr[k] warp-broadcast
    g_h[row * H_DIM + lane] = acc > 0.f ? acc : 0.f;
    g_S[row * H_DIM + lane] = 0.f;
}

// ============================================================
// K2: S[dst] += h[src]  (scatter-add; shared W_edge folded out of the loop)
// 32 threads per edge (lane = feature). Lane 0 loads the two int32
// indices once; broadcast via shfl. atomicAdd result unused -> RED.ADD.
// ============================================================
__global__ void k2_scatter(const int* __restrict__ edge_index,
                           int n_edges, int n_nodes) {
    long long tid = (long long)blockIdx.x * blockDim.x + threadIdx.x;
    int e = (int)(tid >> 5);
    if (e >= n_edges) return;
    int lane = (int)(tid & 31);

    int src = 0, dst = 0;
    if (lane == 0) {
        src = __ldg(&edge_index[e]);            // edge_index[0][e]
        dst = __ldg(&edge_index[n_edges + e]);  // edge_index[1][e]
    }
    src = __shfl_sync(0xFFFFFFFFu, src, 0);
    dst = __shfl_sync(0xFFFFFFFFu, dst, 0);
    // branch-free safety clamp (should be no-ops with valid data)
    src = min(max(src, 0), n_nodes - 1);
    dst = min(max(dst, 0), n_nodes - 1);

    float v = g_h[src * H_DIM + lane];
    atomicAdd(&g_S[dst * H_DIM + lane], v);
}

// ============================================================
// K3: out = S @ W_edge + h @ conv_root + conv_bias
// One warp per node row; lane = output feature.
// ============================================================
__global__ void k3_combine(const float* __restrict__ conv_root,
                           const float* __restrict__ conv_bias,
                           int n_nodes) {
    __shared__ float sWe[H_DIM * H_DIM];  // 4 KB
    __shared__ float sWr[H_DIM * H_DIM];  // 4 KB
    for (int i = threadIdx.x; i < H_DIM * H_DIM; i += blockDim.x) {
        sWe[i] = g_We[i];
        sWr[i] = conv_root[i];
    }
    __syncthreads();

    int warp = threadIdx.x >> 5;
    int lane = threadIdx.x & 31;
    int row = blockIdx.x * (blockDim.x >> 5) + warp;
    if (row >= n_nodes) return;

    const float* Sr = g_S + row * H_DIM;
    const float* hr = g_h + row * H_DIM;
    float acc = conv_bias[lane];
    #pragma unroll
    for (int k = 0; k < H_DIM; k++) {
        acc = fmaf(Sr[k], sWe[k * H_DIM + lane], acc);
        acc = fmaf(hr[k], sWr[k * H_DIM + lane], acc);
    }
    g_out[row * H_DIM + lane] = acc;
}

// ============================================================
// K4: per-edge score.
// p = out[src]*out[dst]; t = relu(p @ lin1_w + lin1_b); score = t @ lin2_w + b2
// One thread per edge; float4 gathers of the L2-resident out-table.
// ============================================================
__global__ void k4_score(const int* __restrict__ edge_index,
                         const float* __restrict__ lin1_w,
                         const float* __restrict__ lin1_b,
                         const float* __restrict__ lin2_w,
                         const float* __restrict__ lin2_b,
                         float* __restrict__ out_score,
                         int n_edges, int n_nodes) {
    __shared__ float sW1[H_DIM * 8];  // 1 KB
    __shared__ float sB1[8];
    __shared__ float sW2[8];
    __shared__ float sB2;
    for (int i = threadIdx.x; i < H_DIM * 8; i += blockDim.x) sW1[i] = lin1_w[i];
    if (threadIdx.x < 8) {
        sB1[threadIdx.x] = lin1_b[threadIdx.x];
        sW2[threadIdx.x] = lin2_w[threadIdx.x];
        if (threadIdx.x == 0) sB2 = lin2_b[0];
    }
    __syncthreads();

    int e = blockIdx.x * blockDim.x + threadIdx.x;
    if (e >= n_edges) return;

    int src = __ldg(&edge_index[e]);
    int dst = __ldg(&edge_index[n_edges + e]);
    src = min(max(src, 0), n_nodes - 1);
    dst = min(max(dst, 0), n_nodes - 1);
    const float4* a4 = (const float4*)(g_out + src * H_DIM);
    const float4* b4 = (const float4*)(g_out + dst * H_DIM);

    float acc[8];
    #pragma unroll
    for (int k = 0; k < 8; k++) acc[k] = sB1[k];

    #pragma unroll
    for (int q = 0; q < H_DIM / 4; q++) {
        float4 a = a4[q];
        float4 b = b4[q];
        float p0 = a.x * b.x, p1 = a.y * b.y, p2 = a.z * b.z, p3 = a.w * b.w;
        int j = q * 4;
        #pragma unroll
        for (int k = 0; k < 8; k++) {
            acc[k] = fmaf(p0, sW1[(j + 0) * 8 + k], acc[k]);
            acc[k] = fmaf(p1, sW1[(j + 1) * 8 + k], acc[k]);
            acc[k] = fmaf(p2, sW1[(j + 2) * 8 + k], acc[k]);
            acc[k] = fmaf(p3, sW1[(j + 3) * 8 + k], acc[k]);
        }
    }

    float score = sB2;
    #pragma unroll
    for (int k = 0; k < 8; k++) {
        float t = acc[k] > 0.f ? acc[k] : 0.f;
        score = fmaf(t, sW2[k], score);
    }
    out_score[e] = score;
}

// ============================================================
// launch
// ============================================================
extern "C" void kernel_launch(void* const* d_in, const int* in_sizes, int n_in,
                              void* d_out, int out_size) {
    const float* x          = (const float*)d_in[0];
    const int*   edge_index = (const int*)d_in[1];   // int64 in JAX -> int32 in harness
    const float* lin0_w     = (const float*)d_in[2];
    const float* lin0_b     = (const float*)d_in[3];
    const float* nn_w1      = (const float*)d_in[4];
    const float* nn_b1      = (const float*)d_in[5];
    const float* nn_w2      = (const float*)d_in[6];
    const float* nn_b2      = (const float*)d_in[7];
    const float* conv_root  = (const float*)d_in[8];
    const float* conv_bias  = (const float*)d_in[9];
    const float* lin1_w     = (const float*)d_in[10];
    const float* lin1_b     = (const float*)d_in[11];
    const float* lin2_w     = (const float*)d_in[12];
    const float* lin2_b     = (const float*)d_in[13];
    float* out_score = (float*)d_out;

    int n_nodes = in_sizes[0] / IN_FEAT;
    int n_edges = in_sizes[1] / 2;

    // K0: shared edge weight matrix (tiny)
    k0_edge_weight<<<1, 256>>>(nn_w1, nn_b1, nn_w2, nn_b2);

    // K1: h = relu(x @ lin0_w + b); S = 0. Warp per row, 8 rows/block.
    {
        int rows_per_block = 256 / 32;
        int blocks = (n_nodes + rows_per_block - 1) / rows_per_block;
        k1_lin0<<<blocks, 256>>>(x, lin0_w, lin0_b, n_nodes);
    }

    // K2: scatter-add h[src] into S[dst]; 32 threads per edge
    {
        long long total = (long long)n_edges * 32;
        int blocks = (int)((total + 255) / 256);
        k2_scatter<<<blocks, 256>>>(edge_index, n_edges, n_nodes);
    }

    // K3: out = S@We + h@Wr + bias
    {
        int rows_per_block = 256 / 32;
        int blocks = (n_nodes + rows_per_block - 1) / rows_per_block;
        k3_combine<<<blocks, 256>>>(conv_root, conv_bias, n_nodes);
    }

    // K4: per-edge scores
    {
        int blocks = (n_edges + 255) / 256;
        k4_score<<<blocks, 256>>>(edge_index, lin1_w, lin1_b, lin2_w, lin2_b,
                                  out_score, n_edges, n_nodes);
    }
}

// round 4
// speedup vs baseline: 1.6410x; 1.6410x over previous
#include <cuda_runtime.h>
#include <stdint.h>

#define N_NODES 50000
#define N_EDGES 400000
#define IN_FEAT 64
#define H_DIM 32

// ---- device scratch (no runtime allocation allowed) ----
__device__ float g_h[N_NODES * H_DIM];     // relu(x@lin0_w + lin0_b)
__device__ float g_S[N_NODES * H_DIM];     // scatter-sum of h[src] at dst
__device__ float g_out[N_NODES * H_DIM];   // node embeddings after NNConv
__device__ float g_We[H_DIM * H_DIM];      // shared per-edge weight matrix

__device__ __forceinline__ void red_add_v4(float* addr, float4 v) {
    asm volatile("red.global.v4.f32.add [%0], {%1, %2, %3, %4};"
                 :: "l"(addr), "f"(v.x), "f"(v.y), "f"(v.z), "f"(v.w)
                 : "memory");
}

// ============================================================
// K0: W_edge = relu(nn_w1 + nn_b1) @ nn_w2 + nn_b2  (shared by all edges,
// since edge_attr == ones((E,1)))
// ============================================================
__global__ void k0_edge_weight(const float* __restrict__ nn_w1,
                               const float* __restrict__ nn_b1,
                               const float* __restrict__ nn_w2,
                               const float* __restrict__ nn_b2) {
    __shared__ float w1[H_DIM];
    int t = threadIdx.x;
    if (t < H_DIM) {
        float v = nn_w1[t] + nn_b1[t];
        w1[t] = v > 0.f ? v : 0.f;
    }
    __syncthreads();
    for (int i = t; i < H_DIM * H_DIM; i += blockDim.x) {
        float acc = nn_b2[i];
        #pragma unroll
        for (int k = 0; k < H_DIM; k++)
            acc += w1[k] * nn_w2[k * (H_DIM * H_DIM) + i];
        g_We[i] = acc;
    }
}

// ============================================================
// K1: h = relu(x @ lin0_w + lin0_b); S = 0.
// THREAD per row. x read as thread-private float4 LDG.128;
// weights broadcast LDS.128 from smem (amortized over warp).
// ============================================================
__global__ void __launch_bounds__(128) k1_lin0(
        const float* __restrict__ x,
        const float* __restrict__ lin0_w,
        const float* __restrict__ lin0_b,
        int n_nodes) {
    __shared__ float4 sw[IN_FEAT * 8];  // [k][j4], 8 KB
    __shared__ float4 sb[8];
    for (int i = threadIdx.x; i < IN_FEAT * 8; i += blockDim.x)
        sw[i] = ((const float4*)lin0_w)[i];
    if (threadIdx.x < 8) sb[threadIdx.x] = ((const float4*)lin0_b)[threadIdx.x];
    __syncthreads();

    int row = blockIdx.x * blockDim.x + threadIdx.x;
    if (row >= n_nodes) return;

    float4 acc[8];
    #pragma unroll
    for (int j = 0; j < 8; j++) acc[j] = sb[j];

    const float4* xr = (const float4*)(x + (size_t)row * IN_FEAT);
    #pragma unroll 4
    for (int q = 0; q < IN_FEAT / 4; q++) {
        float4 xc = __ldg(&xr[q]);
        #pragma unroll
        for (int i = 0; i < 4; i++) {
            float xk = (i == 0) ? xc.x : (i == 1) ? xc.y : (i == 2) ? xc.z : xc.w;
            int k = q * 4 + i;
            #pragma unroll
            for (int j = 0; j < 8; j++) {
                float4 w = sw[k * 8 + j];
                acc[j].x = fmaf(xk, w.x, acc[j].x);
                acc[j].y = fmaf(xk, w.y, acc[j].y);
                acc[j].z = fmaf(xk, w.z, acc[j].z);
                acc[j].w = fmaf(xk, w.w, acc[j].w);
            }
        }
    }

    float4* hr = (float4*)(g_h + row * H_DIM);
    float4* Sr = (float4*)(g_S + row * H_DIM);
    const float4 z = make_float4(0.f, 0.f, 0.f, 0.f);
    #pragma unroll
    for (int j = 0; j < 8; j++) {
        float4 a = acc[j];
        a.x = a.x > 0.f ? a.x : 0.f;
        a.y = a.y > 0.f ? a.y : 0.f;
        a.z = a.z > 0.f ? a.z : 0.f;
        a.w = a.w > 0.f ? a.w : 0.f;
        hr[j] = a;
        Sr[j] = z;
    }
}

// ============================================================
// K2: S[dst] += h[src]  — vector atomics. 8 threads per edge, each
// handles one float4 quarter via red.global.v4.f32.add.
// ============================================================
__global__ void k2_scatter(const int* __restrict__ edge_index,
                           int n_edges, int n_nodes) {
    long long tid = (long long)blockIdx.x * blockDim.x + threadIdx.x;
    int e = (int)(tid >> 3);
    if (e >= n_edges) return;
    int q = (int)(tid & 7);

    int src = __ldg(&edge_index[e]);            // edge_index[0][e]
    int dst = __ldg(&edge_index[n_edges + e]);  // edge_index[1][e]
    src = min(max(src, 0), n_nodes - 1);
    dst = min(max(dst, 0), n_nodes - 1);

    float4 v = __ldg((const float4*)(g_h + src * H_DIM) + q);
    red_add_v4(g_S + dst * H_DIM + q * 4, v);
}

// ============================================================
// K3: out = S @ W_edge + h @ conv_root + conv_bias
// THREAD per row, same layout as K1.
// ============================================================
__global__ void __launch_bounds__(128) k3_combine(
        const float* __restrict__ conv_root,
        const float* __restrict__ conv_bias,
        int n_nodes) {
    __shared__ float4 sWe[H_DIM * 8];  // 4 KB
    __shared__ float4 sWr[H_DIM * 8];  // 4 KB
    __shared__ float4 sb[8];
    for (int i = threadIdx.x; i < H_DIM * 8; i += blockDim.x) {
        sWe[i] = ((const float4*)g_We)[i];
        sWr[i] = ((const float4*)conv_root)[i];
    }
    if (threadIdx.x < 8) sb[threadIdx.x] = ((const float4*)conv_bias)[threadIdx.x];
    __syncthreads();

    int row = blockIdx.x * blockDim.x + threadIdx.x;
    if (row >= n_nodes) return;

    float4 acc[8];
    #pragma unroll
    for (int j = 0; j < 8; j++) acc[j] = sb[j];

    const float4* S4 = (const float4*)(g_S + row * H_DIM);
    const float4* h4 = (const float4*)(g_h + row * H_DIM);
    #pragma unroll 2
    for (int q = 0; q < H_DIM / 4; q++) {
        float4 sc = __ldg(&S4[q]);
        float4 hc = __ldg(&h4[q]);
        #pragma unroll
        for (int i = 0; i < 4; i++) {
            float sk = (i == 0) ? sc.x : (i == 1) ? sc.y : (i == 2) ? sc.z : sc.w;
            float hk = (i == 0) ? hc.x : (i == 1) ? hc.y : (i == 2) ? hc.z : hc.w;
            int k = q * 4 + i;
            #pragma unroll
            for (int j = 0; j < 8; j++) {
                float4 we = sWe[k * 8 + j];
                float4 wr = sWr[k * 8 + j];
                acc[j].x = fmaf(sk, we.x, fmaf(hk, wr.x, acc[j].x));
                acc[j].y = fmaf(sk, we.y, fmaf(hk, wr.y, acc[j].y));
                acc[j].z = fmaf(sk, we.z, fmaf(hk, wr.z, acc[j].z));
                acc[j].w = fmaf(sk, we.w, fmaf(hk, wr.w, acc[j].w));
            }
        }
    }

    float4* orow = (float4*)(g_out + row * H_DIM);
    #pragma unroll
    for (int j = 0; j < 8; j++) orow[j] = acc[j];
}

// ============================================================
// K4: per-edge score.
// p = out[src]*out[dst]; t = relu(p @ lin1_w + lin1_b); score = t @ lin2_w + b2
// One thread per edge; float4 gathers of the L2-resident out-table.
// ============================================================
__global__ void k4_score(const int* __restrict__ edge_index,
                         const float* __restrict__ lin1_w,
                         const float* __restrict__ lin1_b,
                         const float* __restrict__ lin2_w,
                         const float* __restrict__ lin2_b,
                         float* __restrict__ out_score,
                         int n_edges, int n_nodes) {
    __shared__ float sW1[H_DIM * 8];  // 1 KB
    __shared__ float sB1[8];
    __shared__ float sW2[8];
    __shared__ float sB2;
    for (int i = threadIdx.x; i < H_DIM * 8; i += blockDim.x) sW1[i] = lin1_w[i];
    if (threadIdx.x < 8) {
        sB1[threadIdx.x] = lin1_b[threadIdx.x];
        sW2[threadIdx.x] = lin2_w[threadIdx.x];
        if (threadIdx.x == 0) sB2 = lin2_b[0];
    }
    __syncthreads();

    int e = blockIdx.x * blockDim.x + threadIdx.x;
    if (e >= n_edges) return;

    int src = __ldg(&edge_index[e]);
    int dst = __ldg(&edge_index[n_edges + e]);
    src = min(max(src, 0), n_nodes - 1);
    dst = min(max(dst, 0), n_nodes - 1);
    const float4* a4 = (const float4*)(g_out + src * H_DIM);
    const float4* b4 = (const float4*)(g_out + dst * H_DIM);

    float acc[8];
    #pragma unroll
    for (int k = 0; k < 8; k++) acc[k] = sB1[k];

    #pragma unroll
    for (int q = 0; q < H_DIM / 4; q++) {
        float4 a = __ldg(&a4[q]);
        float4 b = __ldg(&b4[q]);
        float p0 = a.x * b.x, p1 = a.y * b.y, p2 = a.z * b.z, p3 = a.w * b.w;
        int j = q * 4;
        #pragma unroll
        for (int k = 0; k < 8; k++) {
            acc[k] = fmaf(p0, sW1[(j + 0) * 8 + k], acc[k]);
            acc[k] = fmaf(p1, sW1[(j + 1) * 8 + k], acc[k]);
            acc[k] = fmaf(p2, sW1[(j + 2) * 8 + k], acc[k]);
            acc[k] = fmaf(p3, sW1[(j + 3) * 8 + k], acc[k]);
        }
    }

    float score = sB2;
    #pragma unroll
    for (int k = 0; k < 8; k++) {
        float t = acc[k] > 0.f ? acc[k] : 0.f;
        score = fmaf(t, sW2[k], score);
    }
    out_score[e] = score;
}

// ============================================================
// launch
// ============================================================
extern "C" void kernel_launch(void* const* d_in, const int* in_sizes, int n_in,
                              void* d_out, int out_size) {
    const float* x          = (const float*)d_in[0];
    const int*   edge_index = (const int*)d_in[1];   // int64 in JAX -> int32 in harness
    const float* lin0_w     = (const float*)d_in[2];
    const float* lin0_b     = (const float*)d_in[3];
    const float* nn_w1      = (const float*)d_in[4];
    const float* nn_b1      = (const float*)d_in[5];
    const float* nn_w2      = (const float*)d_in[6];
    const float* nn_b2      = (const float*)d_in[7];
    const float* conv_root  = (const float*)d_in[8];
    const float* conv_bias  = (const float*)d_in[9];
    const float* lin1_w     = (const float*)d_in[10];
    const float* lin1_b     = (const float*)d_in[11];
    const float* lin2_w     = (const float*)d_in[12];
    const float* lin2_b     = (const float*)d_in[13];
    float* out_score = (float*)d_out;

    int n_nodes = in_sizes[0] / IN_FEAT;
    int n_edges = in_sizes[1] / 2;

    // K0: shared edge weight matrix (tiny)
    k0_edge_weight<<<1, 256>>>(nn_w1, nn_b1, nn_w2, nn_b2);

    // K1: thread per row
    {
        int blocks = (n_nodes + 127) / 128;
        k1_lin0<<<blocks, 128>>>(x, lin0_w, lin0_b, n_nodes);
    }

    // K2: 8 threads per edge, float4 reductions
    {
        long long total = (long long)n_edges * 8;
        int blocks = (int)((total + 255) / 256);
        k2_scatter<<<blocks, 256>>>(edge_index, n_edges, n_nodes);
    }

    // K3: thread per row
    {
        int blocks = (n_nodes + 127) / 128;
        k3_combine<<<blocks, 128>>>(conv_root, conv_bias, n_nodes);
    }

    // K4: thread per edge
    {
        int blocks = (n_edges + 255) / 256;
        k4_score<<<blocks, 256>>>(edge_index, lin1_w, lin1_b, lin2_w, lin2_b,
                                  out_score, n_edges, n_nodes);
    }
}